// round 2
// baseline (speedup 1.0000x reference)
#include <cuda_runtime.h>
#include <cstdint>

// Problem constants (shapes are fixed by the dataset)
#define MAXN 100000
#define MAXE 1600000
#define HDIM 64

// ---------------- scratch (no allocations allowed -> __device__ globals) ----
__device__ int   g_deg[MAXN];
__device__ float g_dinv[MAXN];
__device__ int   g_rowstart[MAXN + 1];
__device__ int   g_cursor[MAXN];
__device__ int   g_esrc[MAXE];
__device__ float g_hs[(size_t)MAXN * HDIM];
__device__ float g_y[(size_t)MAXN * HDIM];

// ---------------- f32x2 helpers (Blackwell packed fp32) ---------------------
__device__ __forceinline__ unsigned long long pack2(float x, float y) {
    unsigned long long r;
    asm("mov.b64 %0, {%1,%2};" : "=l"(r) : "f"(x), "f"(y));
    return r;
}
__device__ __forceinline__ unsigned long long ffma2(unsigned long long a,
                                                    unsigned long long b,
                                                    unsigned long long c) {
    unsigned long long d;
    asm("fma.rn.f32x2 %0, %1, %2, %3;" : "=l"(d) : "l"(a), "l"(b), "l"(c));
    return d;
}
__device__ __forceinline__ unsigned long long mul2(unsigned long long a,
                                                   unsigned long long b) {
    unsigned long long d;
    asm("mul.rn.f32x2 %0, %1, %2;" : "=l"(d) : "l"(a), "l"(b));
    return d;
}
__device__ __forceinline__ float2 unpack2(unsigned long long v) {
    float2 f;
    asm("mov.b64 {%0,%1}, %2;" : "=f"(f.x), "=f"(f.y) : "l"(v));
    return f;
}
__device__ __forceinline__ void lds_v2u64(unsigned addr, unsigned long long& a,
                                          unsigned long long& b) {
    asm("ld.shared.v2.u64 {%0,%1}, [%2];" : "=l"(a), "=l"(b) : "r"(addr));
}

// ---------------- degree / CSR build ----------------------------------------
__global__ void zero_deg_kernel(int n) {
    int i = blockIdx.x * blockDim.x + threadIdx.x;
    if (i < n) g_deg[i] = 0;
}

__global__ void count_deg_kernel(const int* __restrict__ dst, int e) {
    int i = blockIdx.x * blockDim.x + threadIdx.x;
    if (i < e) atomicAdd(&g_deg[dst[i]], 1);
}

__global__ void dinv_kernel(int n) {
    int i = blockIdx.x * blockDim.x + threadIdx.x;
    if (i < n) g_dinv[i] = rsqrtf((float)g_deg[i] + 1.0f);
}

// single-block exclusive scan of g_deg -> g_rowstart (n up to 100K)
__global__ void scan_kernel(int n) {
    __shared__ int part[1024];
    const int t = threadIdx.x;
    const int chunk = (n + 1023) / 1024;
    int b0 = t * chunk; if (b0 > n) b0 = n;
    int b1 = b0 + chunk; if (b1 > n) b1 = n;
    int s = 0;
    for (int i = b0; i < b1; i++) s += g_deg[i];
    part[t] = s;
    __syncthreads();
    // Hillis-Steele inclusive scan
    for (int off = 1; off < 1024; off <<= 1) {
        int v = (t >= off) ? part[t - off] : 0;
        __syncthreads();
        part[t] += v;
        __syncthreads();
    }
    int excl = (t == 0) ? 0 : part[t - 1];
    for (int i = b0; i < b1; i++) {
        g_rowstart[i] = excl;
        excl += g_deg[i];
    }
    if (t == 1023) g_rowstart[n] = part[1023];
}

__global__ void copy_cursor_kernel(int n) {
    int i = blockIdx.x * blockDim.x + threadIdx.x;
    if (i < n) g_cursor[i] = g_rowstart[i];
}

__global__ void place_kernel(const int* __restrict__ src,
                             const int* __restrict__ dst, int e) {
    int i = blockIdx.x * blockDim.x + threadIdx.x;
    if (i < e) {
        int d = dst[i];
        int pos = atomicAdd(&g_cursor[d], 1);
        g_esrc[pos] = src[i];
    }
}

// ---------------- GEMM: hs[row] = (X[row] @ W) * dinv[row] ------------------
// One thread per row. A (the row) lives in registers, W broadcast from smem.
// Packed f32x2 accumulation: 32 FFMA2 + 16 LDS.128 per k -> FMA-pipe-bound.
template <int KDIM>
__global__ void __launch_bounds__(128)
gemm_hs_kernel(const float* __restrict__ X, const float* __restrict__ W, int n) {
    __shared__ float Ws[KDIM * HDIM];
    for (int i = threadIdx.x; i < KDIM * HDIM / 4; i += 128)
        ((float4*)Ws)[i] = ((const float4*)W)[i];
    __syncthreads();

    const int row = blockIdx.x * 128 + threadIdx.x;
    if (row >= n) return;

    unsigned long long acc[32];
#pragma unroll
    for (int p = 0; p < 32; p++) acc[p] = 0ull;

    const float4* xr = (const float4*)(X + (size_t)row * KDIM);
    const unsigned wsh = (unsigned)__cvta_generic_to_shared(Ws);

#pragma unroll 1
    for (int kc = 0; kc < KDIM / 16; kc++) {
        float4 a4[4];
#pragma unroll
        for (int q = 0; q < 4; q++) a4[q] = xr[kc * 4 + q];
        const float* av = reinterpret_cast<const float*>(a4);
#pragma unroll
        for (int kk = 0; kk < 16; kk++) {
            const float a = av[kk];
            const unsigned long long ap = pack2(a, a);
            const unsigned baddr = wsh + (unsigned)((kc * 16 + kk) * HDIM) * 4u;
#pragma unroll
            for (int p = 0; p < 16; p++) {
                unsigned long long b0, b1;
                lds_v2u64(baddr + p * 16u, b0, b1);
                acc[2 * p]     = ffma2(ap, b0, acc[2 * p]);
                acc[2 * p + 1] = ffma2(ap, b1, acc[2 * p + 1]);
            }
        }
    }

    const float dv = __ldg(&g_dinv[row]);
    const unsigned long long dp = pack2(dv, dv);
    float2* op = (float2*)(g_hs + (size_t)row * HDIM);
#pragma unroll
    for (int p = 0; p < 32; p++) op[p] = unpack2(mul2(acc[p], dp));
}

// ---------------- gather + self-loop + bias + LayerNorm + GELU (+ head) -----
// One warp per node. lane l owns columns (2l, 2l+1) as a float2.
template <bool FINAL>
__global__ void __launch_bounds__(256)
gather_finalize_kernel(const float* __restrict__ b, const float* __restrict__ g,
                       const float* __restrict__ be, const float* __restrict__ Wh,
                       const float* __restrict__ bh, float* __restrict__ out,
                       int n) {
    const int warp = (blockIdx.x * blockDim.x + threadIdx.x) >> 5;
    const int lane = threadIdx.x & 31;
    if (warp >= n) return;
    const int node = warp;

    const int s0 = g_rowstart[node];
    const int s1 = g_rowstart[node + 1];

    const float2* hsp = (const float2*)g_hs;
    float2 acc  = make_float2(0.f, 0.f);
    float2 acc2 = make_float2(0.f, 0.f);

    for (int e = s0; e < s1; e += 32) {
        const int cnt = min(32, s1 - e);
        const int s = (lane < cnt) ? __ldg(&g_esrc[e + lane]) : 0;
        int i = 0;
        for (; i + 1 < cnt; i += 2) {
            const int sa = __shfl_sync(0xffffffffu, s, i);
            const int sb = __shfl_sync(0xffffffffu, s, i + 1);
            const float2 va = hsp[(size_t)sa * 32 + lane];
            const float2 vb = hsp[(size_t)sb * 32 + lane];
            acc.x += va.x;  acc.y += va.y;
            acc2.x += vb.x; acc2.y += vb.y;
        }
        if (i < cnt) {
            const int sa = __shfl_sync(0xffffffffu, s, i);
            const float2 va = hsp[(size_t)sa * 32 + lane];
            acc.x += va.x; acc.y += va.y;
        }
    }

    const float dv = g_dinv[node];
    const float2 selfv = hsp[(size_t)node * 32 + lane];
    float v0 = dv * (acc.x + acc2.x + selfv.x) + __ldg(&b[2 * lane]);
    float v1 = dv * (acc.y + acc2.y + selfv.y) + __ldg(&b[2 * lane + 1]);

    // LayerNorm over 64 values (2 per lane)
    float s  = v0 + v1;
    float sq = v0 * v0 + v1 * v1;
#pragma unroll
    for (int o = 16; o > 0; o >>= 1) {
        s  += __shfl_xor_sync(0xffffffffu, s, o);
        sq += __shfl_xor_sync(0xffffffffu, sq, o);
    }
    const float mu   = s * (1.0f / 64.0f);
    float var        = sq * (1.0f / 64.0f) - mu * mu;
    const float rstd = rsqrtf(var + 1e-5f);

    float u0 = (v0 - mu) * rstd * __ldg(&g[2 * lane]) + __ldg(&be[2 * lane]);
    float u1 = (v1 - mu) * rstd * __ldg(&g[2 * lane + 1]) + __ldg(&be[2 * lane + 1]);

    // exact-erf GELU
    u0 = 0.5f * u0 * (1.0f + erff(u0 * 0.70710678118654752f));
    u1 = 0.5f * u1 * (1.0f + erff(u1 * 0.70710678118654752f));

    if (FINAL) {
        float p = u0 * __ldg(&Wh[2 * lane]) + u1 * __ldg(&Wh[2 * lane + 1]);
#pragma unroll
        for (int o = 16; o > 0; o >>= 1) p += __shfl_xor_sync(0xffffffffu, p, o);
        if (lane == 0) out[node] = p + __ldg(&bh[0]);
    } else {
        ((float2*)out)[(size_t)node * 32 + lane] = make_float2(u0, u1);
    }
}

// ---------------- launch -----------------------------------------------------
extern "C" void kernel_launch(void* const* d_in, const int* in_sizes, int n_in,
                              void* d_out, int out_size) {
    const float* x   = (const float*)d_in[0];
    const int*   ei  = (const int*)d_in[1];
    const float* W1  = (const float*)d_in[2];
    const float* b1  = (const float*)d_in[3];
    const float* g1  = (const float*)d_in[4];
    const float* be1 = (const float*)d_in[5];
    const float* W2  = (const float*)d_in[6];
    const float* b2  = (const float*)d_in[7];
    const float* g2  = (const float*)d_in[8];
    const float* be2 = (const float*)d_in[9];
    const float* W3  = (const float*)d_in[10];
    const float* b3  = (const float*)d_in[11];
    const float* g3  = (const float*)d_in[12];
    const float* be3 = (const float*)d_in[13];
    const float* Wh  = (const float*)d_in[14];
    const float* bh  = (const float*)d_in[15];
    float* out = (float*)d_out;

    const int n = in_sizes[0] / 128;
    const int e = in_sizes[1] / 2;
    const int* srcs = ei;
    const int* dsts = ei + e;

    // device scratch pointer for y (kernels reference globals directly; the
    // gather kernel needs it only as its "out" argument for layers 1/2)
    static float* y = nullptr;
    if (!y) cudaGetSymbolAddress((void**)&y, g_y);

    const int EB = (e + 255) / 256;
    const int NB = (n + 255) / 256;
    const int GB = (n + 127) / 128;       // gemm blocks (1 row/thread, 128 thr)
    const int WB = (n + 7) / 8;           // gather blocks (8 warps/block)

    // CSR build (once per launch; reused by all 3 layers) — kernel nodes only
    zero_deg_kernel<<<NB, 256>>>(n);
    count_deg_kernel<<<EB, 256>>>(dsts, e);
    dinv_kernel<<<NB, 256>>>(n);
    scan_kernel<<<1, 1024>>>(n);
    copy_cursor_kernel<<<NB, 256>>>(n);
    place_kernel<<<EB, 256>>>(srcs, dsts, e);

    // Layer 1 (IN=128)
    gemm_hs_kernel<128><<<GB, 128>>>(x, W1, n);
    gather_finalize_kernel<false><<<WB, 256>>>(b1, g1, be1, nullptr, nullptr, y, n);
    // Layer 2 (IN=64)
    gemm_hs_kernel<64><<<GB, 128>>>(y, W2, n);
    gather_finalize_kernel<false><<<WB, 256>>>(b2, g2, be2, nullptr, nullptr, y, n);
    // Layer 3 (IN=64) + fused head
    gemm_hs_kernel<64><<<GB, 128>>>(y, W3, n);
    gather_finalize_kernel<true><<<WB, 256>>>(b3, g3, be3, Wh, bh, out, n);
}

// round 3
// speedup vs baseline: 1.2523x; 1.2523x over previous
#include <cuda_runtime.h>
#include <cstdint>

// Problem constants (shapes are fixed by the dataset)
#define MAXN 100000
#define MAXE 1600000
#define HDIM 64
#define SCAN_B 1024
#define MAXBLK ((MAXN + SCAN_B - 1) / SCAN_B)   // 98

// ---------------- scratch (no allocations allowed -> __device__ globals) ----
__device__ int   g_deg[MAXN];
__device__ float g_dinv[MAXN];
__device__ int   g_rowstart[MAXN + 1];
__device__ int   g_cursor[MAXN];
__device__ int   g_esrc[MAXE];
__device__ int   g_blocksum[1024];
__device__ int   g_blockoff[1024];
__device__ float g_hs[(size_t)MAXN * HDIM];
__device__ float g_y[(size_t)MAXN * HDIM];

// ---------------- f32x2 helpers (Blackwell packed fp32) ---------------------
__device__ __forceinline__ unsigned long long pack2(float x, float y) {
    unsigned long long r;
    asm("mov.b64 %0, {%1,%2};" : "=l"(r) : "f"(x), "f"(y));
    return r;
}
__device__ __forceinline__ unsigned long long ffma2(unsigned long long a,
                                                    unsigned long long b,
                                                    unsigned long long c) {
    unsigned long long d;
    asm("fma.rn.f32x2 %0, %1, %2, %3;" : "=l"(d) : "l"(a), "l"(b), "l"(c));
    return d;
}
__device__ __forceinline__ unsigned long long mul2(unsigned long long a,
                                                   unsigned long long b) {
    unsigned long long d;
    asm("mul.rn.f32x2 %0, %1, %2;" : "=l"(d) : "l"(a), "l"(b));
    return d;
}
__device__ __forceinline__ float2 unpack2(unsigned long long v) {
    float2 f;
    asm("mov.b64 {%0,%1}, %2;" : "=f"(f.x), "=f"(f.y) : "l"(v));
    return f;
}
__device__ __forceinline__ void lds_v2u64(unsigned addr, unsigned long long& a,
                                          unsigned long long& b) {
    asm("ld.shared.v2.u64 {%0,%1}, [%2];" : "=l"(a), "=l"(b) : "r"(addr));
}

// ---------------- degree / CSR build ----------------------------------------
__global__ void zero_deg_kernel(int n) {
    int i = blockIdx.x * blockDim.x + threadIdx.x;
    if (i < n) g_deg[i] = 0;
}

__global__ void count_deg_kernel(const int* __restrict__ dst, int e) {
    int i = blockIdx.x * blockDim.x + threadIdx.x;
    if (i < e) atomicAdd(&g_deg[dst[i]], 1);
}

// Phase A: per-block exclusive scan of g_deg; fused dinv.
__global__ void __launch_bounds__(SCAN_B)
scanA_kernel(int n) {
    __shared__ int sh[SCAN_B];
    const int t = threadIdx.x;
    const int i = blockIdx.x * SCAN_B + t;
    const int v = (i < n) ? g_deg[i] : 0;
    if (i < n) g_dinv[i] = rsqrtf((float)v + 1.0f);
    sh[t] = v;
    __syncthreads();
    // Hillis-Steele inclusive scan over the block
    int acc = v;
#pragma unroll
    for (int off = 1; off < SCAN_B; off <<= 1) {
        int u = (t >= off) ? sh[t - off] : 0;
        __syncthreads();
        acc += u;
        sh[t] = acc;
        __syncthreads();
    }
    if (i < n) g_rowstart[i] = acc - v;     // local exclusive
    if (t == SCAN_B - 1) g_blocksum[blockIdx.x] = acc;
}

// Phase B: single-block exclusive scan of block sums (nb <= 1024).
__global__ void __launch_bounds__(1024)
scanB_kernel(int nb) {
    __shared__ int sh[1024];
    const int t = threadIdx.x;
    const int v = (t < nb) ? g_blocksum[t] : 0;
    sh[t] = v;
    __syncthreads();
    int acc = v;
#pragma unroll
    for (int off = 1; off < 1024; off <<= 1) {
        int u = (t >= off) ? sh[t - off] : 0;
        __syncthreads();
        acc += u;
        sh[t] = acc;
        __syncthreads();
    }
    if (t < nb) g_blockoff[t] = acc - v;    // exclusive
}

// Phase C: add block offsets; write rowstart and cursor (+sentinel).
__global__ void __launch_bounds__(SCAN_B)
scanC_kernel(int n, int e) {
    const int i = blockIdx.x * SCAN_B + threadIdx.x;
    if (i < n) {
        const int r = g_rowstart[i] + g_blockoff[blockIdx.x];
        g_rowstart[i] = r;
        g_cursor[i]   = r;
    }
    if (i == 0) g_rowstart[n] = e;
}

__global__ void place_kernel(const int* __restrict__ src,
                             const int* __restrict__ dst, int e) {
    int i = blockIdx.x * blockDim.x + threadIdx.x;
    if (i < e) {
        int d = dst[i];
        int pos = atomicAdd(&g_cursor[d], 1);
        g_esrc[pos] = src[i];
    }
}

// ---------------- GEMM: hs[row] = (X[row] @ W) * dinv[row] ------------------
// One thread per row. A (the row) lives in registers, W broadcast from smem.
// Packed f32x2 accumulation: 32 FFMA2 + 16 LDS.128 per k -> FMA-pipe-bound.
template <int KDIM>
__global__ void __launch_bounds__(128)
gemm_hs_kernel(const float* __restrict__ X, const float* __restrict__ W, int n) {
    __shared__ float Ws[KDIM * HDIM];
    for (int i = threadIdx.x; i < KDIM * HDIM / 4; i += 128)
        ((float4*)Ws)[i] = ((const float4*)W)[i];
    __syncthreads();

    const int row = blockIdx.x * 128 + threadIdx.x;
    if (row >= n) return;

    unsigned long long acc[32];
#pragma unroll
    for (int p = 0; p < 32; p++) acc[p] = 0ull;

    const float4* xr = (const float4*)(X + (size_t)row * KDIM);
    const unsigned wsh = (unsigned)__cvta_generic_to_shared(Ws);

#pragma unroll 1
    for (int kc = 0; kc < KDIM / 16; kc++) {
        float4 a4[4];
#pragma unroll
        for (int q = 0; q < 4; q++) a4[q] = xr[kc * 4 + q];
        const float* av = reinterpret_cast<const float*>(a4);
#pragma unroll
        for (int kk = 0; kk < 16; kk++) {
            const float a = av[kk];
            const unsigned long long ap = pack2(a, a);
            const unsigned baddr = wsh + (unsigned)((kc * 16 + kk) * HDIM) * 4u;
#pragma unroll
            for (int p = 0; p < 16; p++) {
                unsigned long long b0, b1;
                lds_v2u64(baddr + p * 16u, b0, b1);
                acc[2 * p]     = ffma2(ap, b0, acc[2 * p]);
                acc[2 * p + 1] = ffma2(ap, b1, acc[2 * p + 1]);
            }
        }
    }

    const float dv = __ldg(&g_dinv[row]);
    const unsigned long long dp = pack2(dv, dv);
    float2* op = (float2*)(g_hs + (size_t)row * HDIM);
#pragma unroll
    for (int p = 0; p < 32; p++) op[p] = unpack2(mul2(acc[p], dp));
}

// ---------------- gather + self-loop + bias + LayerNorm + GELU (+ head) -----
// One warp per node. lane l owns columns (2l, 2l+1) as a float2.
template <bool FINAL>
__global__ void __launch_bounds__(256)
gather_finalize_kernel(const float* __restrict__ b, const float* __restrict__ g,
                       const float* __restrict__ be, const float* __restrict__ Wh,
                       const float* __restrict__ bh, float* __restrict__ out,
                       int n) {
    const int warp = (blockIdx.x * blockDim.x + threadIdx.x) >> 5;
    const int lane = threadIdx.x & 31;
    if (warp >= n) return;
    const int node = warp;

    const int s0 = g_rowstart[node];
    const int s1 = g_rowstart[node + 1];

    const float2* hsp = (const float2*)g_hs;
    float2 acc  = make_float2(0.f, 0.f);
    float2 acc2 = make_float2(0.f, 0.f);

    for (int e = s0; e < s1; e += 32) {
        const int cnt = min(32, s1 - e);
        const int s = (lane < cnt) ? __ldg(&g_esrc[e + lane]) : 0;
        int i = 0;
        for (; i + 1 < cnt; i += 2) {
            const int sa = __shfl_sync(0xffffffffu, s, i);
            const int sb = __shfl_sync(0xffffffffu, s, i + 1);
            const float2 va = hsp[(size_t)sa * 32 + lane];
            const float2 vb = hsp[(size_t)sb * 32 + lane];
            acc.x += va.x;  acc.y += va.y;
            acc2.x += vb.x; acc2.y += vb.y;
        }
        if (i < cnt) {
            const int sa = __shfl_sync(0xffffffffu, s, i);
            const float2 va = hsp[(size_t)sa * 32 + lane];
            acc.x += va.x; acc.y += va.y;
        }
    }

    const float dv = g_dinv[node];
    const float2 selfv = hsp[(size_t)node * 32 + lane];
    float v0 = dv * (acc.x + acc2.x + selfv.x) + __ldg(&b[2 * lane]);
    float v1 = dv * (acc.y + acc2.y + selfv.y) + __ldg(&b[2 * lane + 1]);

    // LayerNorm over 64 values (2 per lane)
    float s  = v0 + v1;
    float sq = v0 * v0 + v1 * v1;
#pragma unroll
    for (int o = 16; o > 0; o >>= 1) {
        s  += __shfl_xor_sync(0xffffffffu, s, o);
        sq += __shfl_xor_sync(0xffffffffu, sq, o);
    }
    const float mu   = s * (1.0f / 64.0f);
    float var        = sq * (1.0f / 64.0f) - mu * mu;
    const float rstd = rsqrtf(var + 1e-5f);

    float u0 = (v0 - mu) * rstd * __ldg(&g[2 * lane]) + __ldg(&be[2 * lane]);
    float u1 = (v1 - mu) * rstd * __ldg(&g[2 * lane + 1]) + __ldg(&be[2 * lane + 1]);

    // exact-erf GELU
    u0 = 0.5f * u0 * (1.0f + erff(u0 * 0.70710678118654752f));
    u1 = 0.5f * u1 * (1.0f + erff(u1 * 0.70710678118654752f));

    if (FINAL) {
        float p = u0 * __ldg(&Wh[2 * lane]) + u1 * __ldg(&Wh[2 * lane + 1]);
#pragma unroll
        for (int o = 16; o > 0; o >>= 1) p += __shfl_xor_sync(0xffffffffu, p, o);
        if (lane == 0) out[node] = p + __ldg(&bh[0]);
    } else {
        ((float2*)out)[(size_t)node * 32 + lane] = make_float2(u0, u1);
    }
}

// ---------------- launch -----------------------------------------------------
extern "C" void kernel_launch(void* const* d_in, const int* in_sizes, int n_in,
                              void* d_out, int out_size) {
    const float* x   = (const float*)d_in[0];
    const int*   ei  = (const int*)d_in[1];
    const float* W1  = (const float*)d_in[2];
    const float* b1  = (const float*)d_in[3];
    const float* g1  = (const float*)d_in[4];
    const float* be1 = (const float*)d_in[5];
    const float* W2  = (const float*)d_in[6];
    const float* b2  = (const float*)d_in[7];
    const float* g2  = (const float*)d_in[8];
    const float* be2 = (const float*)d_in[9];
    const float* W3  = (const float*)d_in[10];
    const float* b3  = (const float*)d_in[11];
    const float* g3  = (const float*)d_in[12];
    const float* be3 = (const float*)d_in[13];
    const float* Wh  = (const float*)d_in[14];
    const float* bh  = (const float*)d_in[15];
    float* out = (float*)d_out;

    const int n = in_sizes[0] / 128;
    const int e = in_sizes[1] / 2;
    const int* srcs = ei;
    const int* dsts = ei + e;

    static float* y = nullptr;
    if (!y) cudaGetSymbolAddress((void**)&y, g_y);

    const int EB = (e + 255) / 256;
    const int NB = (n + 255) / 256;
    const int SB = (n + SCAN_B - 1) / SCAN_B;  // scan blocks (<= 98)
    const int GB = (n + 127) / 128;            // gemm blocks
    const int WB = (n + 7) / 8;                // gather blocks (8 warps/block)

    // CSR build (once per launch; reused by all 3 layers)
    zero_deg_kernel<<<NB, 256>>>(n);
    count_deg_kernel<<<EB, 256>>>(dsts, e);
    scanA_kernel<<<SB, SCAN_B>>>(n);           // + fused dinv
    scanB_kernel<<<1, 1024>>>(SB);
    scanC_kernel<<<SB, SCAN_B>>>(n, e);        // + fused cursor init
    place_kernel<<<EB, 256>>>(srcs, dsts, e);

    // Layer 1 (IN=128)
    gemm_hs_kernel<128><<<GB, 128>>>(x, W1, n);
    gather_finalize_kernel<false><<<WB, 256>>>(b1, g1, be1, nullptr, nullptr, y, n);
    // Layer 2 (IN=64)
    gemm_hs_kernel<64><<<GB, 128>>>(y, W2, n);
    gather_finalize_kernel<false><<<WB, 256>>>(b2, g2, be2, nullptr, nullptr, y, n);
    // Layer 3 (IN=64) + fused head
    gemm_hs_kernel<64><<<GB, 128>>>(y, W3, n);
    gather_finalize_kernel<true><<<WB, 256>>>(b3, g3, be3, Wh, bh, out, n);
}

// round 4
// speedup vs baseline: 1.2615x; 1.0073x over previous
#include <cuda_runtime.h>
#include <cstdint>

// Problem constants (shapes are fixed by the dataset)
#define MAXN 100000
#define MAXE 1600000
#define HDIM 64
#define SCAN_B 1024

// ---------------- scratch (no allocations allowed -> __device__ globals) ----
__device__ int   g_deg[MAXN];                 // zero at load; re-zeroed by scanA
__device__ float g_dinv[MAXN];
__device__ int   g_rowstart[MAXN + 1];
__device__ int   g_cursor[MAXN];
__device__ int   g_esrc[MAXE];
__device__ int   g_blocksum[1024];
__device__ int   g_blockoff[1024];
__device__ float g_hs[(size_t)MAXN * HDIM];
__device__ float g_y[(size_t)MAXN * HDIM];

// ---------------- f32x2 helpers (Blackwell packed fp32) ---------------------
__device__ __forceinline__ unsigned long long pack2(float x, float y) {
    unsigned long long r;
    asm("mov.b64 %0, {%1,%2};" : "=l"(r) : "f"(x), "f"(y));
    return r;
}
__device__ __forceinline__ unsigned long long ffma2(unsigned long long a,
                                                    unsigned long long b,
                                                    unsigned long long c) {
    unsigned long long d;
    asm("fma.rn.f32x2 %0, %1, %2, %3;" : "=l"(d) : "l"(a), "l"(b), "l"(c));
    return d;
}
__device__ __forceinline__ unsigned long long add2(unsigned long long a,
                                                   unsigned long long b) {
    unsigned long long d;
    asm("add.rn.f32x2 %0, %1, %2;" : "=l"(d) : "l"(a), "l"(b));
    return d;
}
__device__ __forceinline__ unsigned long long mul2(unsigned long long a,
                                                   unsigned long long b) {
    unsigned long long d;
    asm("mul.rn.f32x2 %0, %1, %2;" : "=l"(d) : "l"(a), "l"(b));
    return d;
}
__device__ __forceinline__ float2 unpack2(unsigned long long v) {
    float2 f;
    asm("mov.b64 {%0,%1}, %2;" : "=f"(f.x), "=f"(f.y) : "l"(v));
    return f;
}
__device__ __forceinline__ void lds_v2u64(unsigned addr, unsigned long long& a,
                                          unsigned long long& b) {
    asm("ld.shared.v2.u64 {%0,%1}, [%2];" : "=l"(a), "=l"(b) : "r"(addr));
}

// ---------------- CSR build --------------------------------------------------
__global__ void count_deg_kernel(const int* __restrict__ dst, int e) {
    int i = blockIdx.x * blockDim.x + threadIdx.x;
    if (i < e) atomicAdd(&g_deg[dst[i]], 1);
}

// Phase A: per-block exclusive scan of g_deg; fused dinv; re-zero deg.
__global__ void __launch_bounds__(SCAN_B)
scanA_kernel(int n) {
    __shared__ int sh[SCAN_B];
    const int t = threadIdx.x;
    const int i = blockIdx.x * SCAN_B + t;
    const int v = (i < n) ? g_deg[i] : 0;
    if (i < n) {
        g_dinv[i] = rsqrtf((float)v + 1.0f);
        g_deg[i] = 0;                       // ready for next replay
    }
    sh[t] = v;
    __syncthreads();
    int acc = v;
#pragma unroll
    for (int off = 1; off < SCAN_B; off <<= 1) {
        int u = (t >= off) ? sh[t - off] : 0;
        __syncthreads();
        acc += u;
        sh[t] = acc;
        __syncthreads();
    }
    if (i < n) g_rowstart[i] = acc - v;     // local exclusive
    if (t == SCAN_B - 1) g_blocksum[blockIdx.x] = acc;
}

// Phase B: single-block exclusive scan of block sums (nb <= 1024).
__global__ void __launch_bounds__(1024)
scanB_kernel(int nb) {
    __shared__ int sh[1024];
    const int t = threadIdx.x;
    const int v = (t < nb) ? g_blocksum[t] : 0;
    sh[t] = v;
    __syncthreads();
    int acc = v;
#pragma unroll
    for (int off = 1; off < 1024; off <<= 1) {
        int u = (t >= off) ? sh[t - off] : 0;
        __syncthreads();
        acc += u;
        sh[t] = acc;
        __syncthreads();
    }
    if (t < nb) g_blockoff[t] = acc - v;    // exclusive
}

// Phase C: add block offsets; write rowstart and cursor (+sentinel).
__global__ void __launch_bounds__(SCAN_B)
scanC_kernel(int n, int e) {
    const int i = blockIdx.x * SCAN_B + threadIdx.x;
    if (i < n) {
        const int r = g_rowstart[i] + g_blockoff[blockIdx.x];
        g_rowstart[i] = r;
        g_cursor[i]   = r;
    }
    if (i == 0) g_rowstart[n] = e;
}

__global__ void place_kernel(const int* __restrict__ src,
                             const int* __restrict__ dst, int e) {
    int i = blockIdx.x * blockDim.x + threadIdx.x;
    if (i < e) {
        int d = dst[i];
        int pos = atomicAdd(&g_cursor[d], 1);
        g_esrc[pos] = src[i];
    }
}

// ---------------- GEMM: hs[row] = (X[row] @ W) * dinv[row] ------------------
template <int KDIM>
__global__ void __launch_bounds__(128)
gemm_hs_kernel(const float* __restrict__ X, const float* __restrict__ W, int n) {
    __shared__ float Ws[KDIM * HDIM];
    for (int i = threadIdx.x; i < KDIM * HDIM / 4; i += 128)
        ((float4*)Ws)[i] = ((const float4*)W)[i];
    __syncthreads();

    const int row = blockIdx.x * 128 + threadIdx.x;
    if (row >= n) return;

    unsigned long long acc[32];
#pragma unroll
    for (int p = 0; p < 32; p++) acc[p] = 0ull;

    const float4* xr = (const float4*)(X + (size_t)row * KDIM);
    const unsigned wsh = (unsigned)__cvta_generic_to_shared(Ws);

#pragma unroll 1
    for (int kc = 0; kc < KDIM / 16; kc++) {
        float4 a4[4];
#pragma unroll
        for (int q = 0; q < 4; q++) a4[q] = xr[kc * 4 + q];
        const float* av = reinterpret_cast<const float*>(a4);
#pragma unroll
        for (int kk = 0; kk < 16; kk++) {
            const float a = av[kk];
            const unsigned long long ap = pack2(a, a);
            const unsigned baddr = wsh + (unsigned)((kc * 16 + kk) * HDIM) * 4u;
#pragma unroll
            for (int p = 0; p < 16; p++) {
                unsigned long long b0, b1;
                lds_v2u64(baddr + p * 16u, b0, b1);
                acc[2 * p]     = ffma2(ap, b0, acc[2 * p]);
                acc[2 * p + 1] = ffma2(ap, b1, acc[2 * p + 1]);
            }
        }
    }

    const float dv = __ldg(&g_dinv[row]);
    const unsigned long long dp = pack2(dv, dv);
    float2* op = (float2*)(g_hs + (size_t)row * HDIM);
#pragma unroll
    for (int p = 0; p < 32; p++) op[p] = unpack2(mul2(acc[p], dp));
}

// ---------------- gather + self-loop + bias + LayerNorm + GELU (+ head) -----
// One warp per node. lane l owns columns (2l, 2l+1) as a packed f32x2 (u64).
// 4-wide unrolled edge loop: 4 loads in flight, packed adds.
template <bool FINAL>
__global__ void __launch_bounds__(256)
gather_finalize_kernel(const float* __restrict__ b, const float* __restrict__ g,
                       const float* __restrict__ be, const float* __restrict__ Wh,
                       const float* __restrict__ bh, float* __restrict__ out,
                       int n) {
    const int warp = (blockIdx.x * blockDim.x + threadIdx.x) >> 5;
    const int lane = threadIdx.x & 31;
    if (warp >= n) return;
    const int node = warp;

    const int s0 = g_rowstart[node];
    const int s1 = g_rowstart[node + 1];

    const unsigned long long* hsp = (const unsigned long long*)g_hs;

    unsigned long long a0 = 0ull, a1 = 0ull, a2 = 0ull, a3 = 0ull;

    for (int e = s0; e < s1; e += 32) {
        const int cnt = min(32, s1 - e);
        const int s = (lane < cnt) ? __ldg(&g_esrc[e + lane]) : 0;
        int i = 0;
        for (; i + 4 <= cnt; i += 4) {
            const int sa = __shfl_sync(0xffffffffu, s, i);
            const int sb = __shfl_sync(0xffffffffu, s, i + 1);
            const int sc = __shfl_sync(0xffffffffu, s, i + 2);
            const int sd = __shfl_sync(0xffffffffu, s, i + 3);
            const unsigned long long va = __ldg(&hsp[(size_t)sa * 32 + lane]);
            const unsigned long long vb = __ldg(&hsp[(size_t)sb * 32 + lane]);
            const unsigned long long vc = __ldg(&hsp[(size_t)sc * 32 + lane]);
            const unsigned long long vd = __ldg(&hsp[(size_t)sd * 32 + lane]);
            a0 = add2(a0, va);
            a1 = add2(a1, vb);
            a2 = add2(a2, vc);
            a3 = add2(a3, vd);
        }
        for (; i < cnt; i++) {
            const int sa = __shfl_sync(0xffffffffu, s, i);
            a0 = add2(a0, __ldg(&hsp[(size_t)sa * 32 + lane]));
        }
    }

    // total = edges + self-loop term
    unsigned long long tot = add2(add2(a0, a1), add2(a2, a3));
    tot = add2(tot, __ldg(&hsp[(size_t)node * 32 + lane]));
    const float2 t2 = unpack2(tot);

    const float dv = g_dinv[node];
    float v0 = dv * t2.x + __ldg(&b[2 * lane]);
    float v1 = dv * t2.y + __ldg(&b[2 * lane + 1]);

    // LayerNorm over 64 values (2 per lane)
    float s  = v0 + v1;
    float sq = v0 * v0 + v1 * v1;
#pragma unroll
    for (int o = 16; o > 0; o >>= 1) {
        s  += __shfl_xor_sync(0xffffffffu, s, o);
        sq += __shfl_xor_sync(0xffffffffu, sq, o);
    }
    const float mu   = s * (1.0f / 64.0f);
    float var        = sq * (1.0f / 64.0f) - mu * mu;
    const float rstd = rsqrtf(var + 1e-5f);

    float u0 = (v0 - mu) * rstd * __ldg(&g[2 * lane]) + __ldg(&be[2 * lane]);
    float u1 = (v1 - mu) * rstd * __ldg(&g[2 * lane + 1]) + __ldg(&be[2 * lane + 1]);

    // exact-erf GELU
    u0 = 0.5f * u0 * (1.0f + erff(u0 * 0.70710678118654752f));
    u1 = 0.5f * u1 * (1.0f + erff(u1 * 0.70710678118654752f));

    if (FINAL) {
        float p = u0 * __ldg(&Wh[2 * lane]) + u1 * __ldg(&Wh[2 * lane + 1]);
#pragma unroll
        for (int o = 16; o > 0; o >>= 1) p += __shfl_xor_sync(0xffffffffu, p, o);
        if (lane == 0) out[node] = p + __ldg(&bh[0]);
    } else {
        ((float2*)out)[(size_t)node * 32 + lane] = make_float2(u0, u1);
    }
}

// ---------------- launch -----------------------------------------------------
extern "C" void kernel_launch(void* const* d_in, const int* in_sizes, int n_in,
                              void* d_out, int out_size) {
    const float* x   = (const float*)d_in[0];
    const int*   ei  = (const int*)d_in[1];
    const float* W1  = (const float*)d_in[2];
    const float* b1  = (const float*)d_in[3];
    const float* g1  = (const float*)d_in[4];
    const float* be1 = (const float*)d_in[5];
    const float* W2  = (const float*)d_in[6];
    const float* b2  = (const float*)d_in[7];
    const float* g2  = (const float*)d_in[8];
    const float* be2 = (const float*)d_in[9];
    const float* W3  = (const float*)d_in[10];
    const float* b3  = (const float*)d_in[11];
    const float* g3  = (const float*)d_in[12];
    const float* be3 = (const float*)d_in[13];
    const float* Wh  = (const float*)d_in[14];
    const float* bh  = (const float*)d_in[15];
    float* out = (float*)d_out;

    const int n = in_sizes[0] / 128;
    const int e = in_sizes[1] / 2;
    const int* srcs = ei;
    const int* dsts = ei + e;

    static float* y = nullptr;
    if (!y) cudaGetSymbolAddress((void**)&y, g_y);

    const int EB = (e + 255) / 256;
    const int SB = (n + SCAN_B - 1) / SCAN_B;  // scan blocks (<= 98)
    const int GB = (n + 127) / 128;            // gemm blocks
    const int WB = (n + 7) / 8;                // gather blocks (8 warps/block)

    // CSR build (deg is zeroed at module load and re-zeroed by scanA)
    count_deg_kernel<<<EB, 256>>>(dsts, e);
    scanA_kernel<<<SB, SCAN_B>>>(n);           // + fused dinv + deg re-zero
    scanB_kernel<<<1, 1024>>>(SB);
    scanC_kernel<<<SB, SCAN_B>>>(n, e);        // + fused cursor init
    place_kernel<<<EB, 256>>>(srcs, dsts, e);

    // Layer 1 (IN=128)
    gemm_hs_kernel<128><<<GB, 128>>>(x, W1, n);
    gather_finalize_kernel<false><<<WB, 256>>>(b1, g1, be1, nullptr, nullptr, y, n);
    // Layer 2 (IN=64)
    gemm_hs_kernel<64><<<GB, 128>>>(y, W2, n);
    gather_finalize_kernel<false><<<WB, 256>>>(b2, g2, be2, nullptr, nullptr, y, n);
    // Layer 3 (IN=64) + fused head
    gemm_hs_kernel<64><<<GB, 128>>>(y, W3, n);
    gather_finalize_kernel<true><<<WB, 256>>>(b3, g3, be3, Wh, bh, out, n);
}